// round 12
// baseline (speedup 1.0000x reference)
#include <cuda_runtime.h>
#include <cstddef>

#define BB 256
#define TT 19
#define NK 512
#define IMG 1728

// ------------------------- scratch -------------------------
__device__ float g_c0[(size_t)TT * 1048576];
__device__ float g_h1all[(size_t)TT * 1048576];
__device__ float g_h2h[4864 * 256];
__device__ float g_h2fin[BB * 256];
__device__ float g_w1e[1048576];
__device__ float g_w1d[524288];
__device__ float g_linT[65536];
__device__ float g_linTD[16384];
__device__ float g_embsq[NK];
__device__ float g_q[1048576];
__device__ int   g_counts[NK];
__device__ float g_vqpart[BB];
__device__ float g_klpart[BB];
__device__ float g_h2s[BB * 128];
__device__ float g_dech2all[20 * BB * 128];
__device__ float g_h1l[(size_t)20 * 1048576];
__device__ float g_hist[(size_t)19 * 1048576];

__global__ void k_init() { if (threadIdx.x < NK) g_counts[threadIdx.x] = 0; }

__global__ void k_pre(const float* __restrict__ encw1,
                      const float* __restrict__ decw1,
                      const float* __restrict__ enclin,
                      const float* __restrict__ declin,
                      const float* __restrict__ emb) {
    int i = blockIdx.x * 256 + threadIdx.x;
    if (i < 1048576) {
        int o = i >> 12, rem = i & 4095, p = rem >> 6, c = rem & 63;
        g_w1e[i] = encw1[(o << 12) + (c << 6) + p];
    } else if (i < 1572864) {
        int j = i - 1048576;
        int c = j >> 12, rem = j & 4095, p = rem >> 6, o = rem & 63;
        g_w1d[j] = decw1[(c << 12) + (o << 6) + p];
    } else if (i < 1638400) {
        int j = i - 1572864; int k = j >> 8, o = j & 255;
        g_linT[j] = enclin[o * 256 + k];
    } else if (i < 1654784) {
        int j = i - 1638400; int k = j >> 7, o = j & 127;
        g_linTD[j] = declin[o * 128 + k];
    } else if (i < 1655296) {
        int k = i - 1654784;
        float s = 0.f;
        for (int c = 0; c < 64; c++) { float e = emb[k * 64 + c]; s += e * e; }
        g_embsq[k] = s;
    }
}

__global__ __launch_bounds__(256) void k_conv0(const float* __restrict__ x,
                                               const float* __restrict__ w,
                                               const float* __restrict__ bias) {
    __shared__ float sx[IMG];
    __shared__ float sw[IMG];
    int bid = blockIdx.x;
    int t = bid % TT, b = bid / TT;
    const float* xp = x + (size_t)(b * TT + t) * IMG;
    int tid = threadIdx.x;
    for (int i = tid; i < IMG; i += 256) { sx[i] = xp[i]; sw[i] = w[i]; }
    __syncthreads();
    int o = tid & 63, pg = tid >> 6;
    float wr[27];
#pragma unroll
    for (int u = 0; u < 27; u++) wr[u] = sw[o * 27 + u];
    float bo = bias[o];
    float* outp = g_c0 + ((size_t)t * BB + b) * 4096;
#pragma unroll
    for (int k = 0; k < 16; k++) {
        int p = pg + 4 * k, h = p >> 3, ww = p & 7;
        const float* xb = sx + h * 72 + ww * 3;
        float acc = bo;
#pragma unroll
        for (int c = 0; c < 3; c++)
#pragma unroll
            for (int ki = 0; ki < 3; ki++)
#pragma unroll
                for (int kj = 0; kj < 3; kj++)
                    acc += xb[c * 576 + ki * 24 + kj] * wr[c * 9 + ki * 3 + kj];
        outp[p * 64 + o] = acc;
    }
}

// ------------- fused h1 recurrence chain (enc mode=0 / dec mode=1) ----------
// 256 blocks x 128 threads; block owns 64 rows; ping-pong state, 1 sync/step.
__global__ __launch_bounds__(128) void k_chain(const float* __restrict__ R,
                                               const float* __restrict__ addb,
                                               const float* __restrict__ initp,
                                               const float* __restrict__ b1,
                                               const float* __restrict__ b2,
                                               float* __restrict__ outb,
                                               int mode) {
    __shared__ float shA[2][64][68];  // [buf][c][row]
    __shared__ float sR[64][68];      // [c][o]
    int tid = threadIdx.x;
    int row0 = blockIdx.x * 64;
    int rg = (tid >> 4) << 3;         // 8 rows
    int cg = (tid & 15) << 2;         // 4 cols
    for (int q = tid; q < 4096; q += 128) sR[q & 63][q >> 6] = R[q];
    float bias[4];
#pragma unroll
    for (int j = 0; j < 4; j++) bias[j] = b1[cg + j] + (b2 ? b2[cg + j] : 0.f);
    for (int q = tid; q < 1024; q += 128) {
        int r = q >> 4, c4 = (q & 15) << 2;
        float4 v = *(const float4*)&initp[(size_t)(row0 + r) * 64 + c4];
        if (!mode) {
            v.x = fmaxf(v.x, 0.f); v.y = fmaxf(v.y, 0.f);
            v.z = fmaxf(v.z, 0.f); v.w = fmaxf(v.w, 0.f);
            *(float4*)&outb[(size_t)(row0 + r) * 64 + c4] = v;
        }
        shA[0][c4][r] = v.x; shA[0][c4 + 1][r] = v.y;
        shA[0][c4 + 2][r] = v.z; shA[0][c4 + 3][r] = v.w;
    }
    __syncthreads();
    int tot = mode ? 20 : 18;
    int cur = 0;
    for (int it = 0; it < tot; it++) {
        int t = mode ? it : it + 1;
        float acc[8][4];
#pragma unroll
        for (int i = 0; i < 8; i++)
#pragma unroll
            for (int j = 0; j < 4; j++) acc[i][j] = 0.f;
#pragma unroll 4
        for (int c = 0; c < 64; c++) {
            float4 a0 = *(float4*)&shA[cur][c][rg];
            float4 a1 = *(float4*)&shA[cur][c][rg + 4];
            float4 w = *(float4*)&sR[c][cg];
            float av[8] = {a0.x, a0.y, a0.z, a0.w, a1.x, a1.y, a1.z, a1.w};
            float wv[4] = {w.x, w.y, w.z, w.w};
#pragma unroll
            for (int i = 0; i < 8; i++)
#pragma unroll
                for (int j = 0; j < 4; j++) acc[i][j] += av[i] * wv[j];
        }
        const float* add = addb + (size_t)t * 1048576;
        float* op = mode ? (t >= 1 ? outb + (size_t)(t - 1) * 1048576 : (float*)0)
                         : outb + (size_t)t * 1048576;
        int nxt = cur ^ 1;
#pragma unroll
        for (int i = 0; i < 8; i++) {
            int r = row0 + rg + i;
            float4 ad = *(const float4*)&add[(size_t)r * 64 + cg];
            float4 res;
            res.x = fmaxf(acc[i][0] + ad.x + bias[0], 0.f);
            res.y = fmaxf(acc[i][1] + ad.y + bias[1], 0.f);
            res.z = fmaxf(acc[i][2] + ad.z + bias[2], 0.f);
            res.w = fmaxf(acc[i][3] + ad.w + bias[3], 0.f);
            if (op) *(float4*)&op[(size_t)r * 64 + cg] = res;
            shA[nxt][cg][rg + i] = res.x; shA[nxt][cg + 1][rg + i] = res.y;
            shA[nxt][cg + 2][rg + i] = res.z; shA[nxt][cg + 3][rg + i] = res.w;
        }
        cur = nxt;
        __syncthreads();
    }
}

// ------------- batched contract GEMM  M=4864 N=256 K=4096 -------------------
// 256 threads, 64x64 tile, 4x4/thread, reg-prefetch + double-buffered smem.
// Dynamic smem: 2 bufs x (A + B) x 64x68 floats = 69632 bytes.
__global__ __launch_bounds__(256) void k_contract(const float* __restrict__ w1b) {
    extern __shared__ float dsm[];
    float (*sAT)[64][68] = (float (*)[64][68])dsm;                  // [2][64][68]
    float (*sB)[64][68]  = (float (*)[64][68])(dsm + 2 * 64 * 68);  // [2][64][68]
    int col0 = blockIdx.x << 6, row0 = blockIdx.y << 6;
    int tid = threadIdx.x, rg = (tid >> 4) << 2, cg = (tid & 15) << 2;
    int srow = tid >> 6;          // 0..3 base row for staging
    int skk = tid & 63;           // k within tile
    float acc[4][4] = {};
    float pa[16], pb[16];
    // preload k0 = 0 and stage into buf 0
#pragma unroll
    for (int it = 0; it < 16; it++) {
        int row = srow + (it << 2);
        pa[it] = g_h1all[(size_t)(row0 + row) * 4096 + skk];
        pb[it] = g_w1e[(size_t)(col0 + row) * 4096 + skk];
    }
#pragma unroll
    for (int it = 0; it < 16; it++) {
        int row = srow + (it << 2);
        sAT[0][skk][row] = pa[it];
        sB[0][skk][row] = pb[it];
    }
    __syncthreads();
    for (int k0 = 0; k0 < 4096; k0 += 64) {
        int buf = (k0 >> 6) & 1;
        if (k0 + 64 < 4096) {
#pragma unroll
            for (int it = 0; it < 16; it++) {
                int row = srow + (it << 2);
                pa[it] = g_h1all[(size_t)(row0 + row) * 4096 + k0 + 64 + skk];
                pb[it] = g_w1e[(size_t)(col0 + row) * 4096 + k0 + 64 + skk];
            }
        }
#pragma unroll 8
        for (int kk = 0; kk < 64; kk++) {
            float4 av = *(const float4*)&sAT[buf][kk][rg];
            float4 bv = *(const float4*)&sB[buf][kk][cg];
            float a[4] = {av.x, av.y, av.z, av.w};
            float b[4] = {bv.x, bv.y, bv.z, bv.w};
#pragma unroll
            for (int i = 0; i < 4; i++)
#pragma unroll
                for (int j = 0; j < 4; j++) acc[i][j] += a[i] * b[j];
        }
        if (k0 + 64 < 4096) {
#pragma unroll
            for (int it = 0; it < 16; it++) {
                int row = srow + (it << 2);
                sAT[buf ^ 1][skk][row] = pa[it];
                sB[buf ^ 1][skk][row] = pb[it];
            }
        }
        __syncthreads();
    }
#pragma unroll
    for (int i = 0; i < 4; i++)
#pragma unroll
        for (int j = 0; j < 4; j++) {
            int gc = col0 + cg + j;
            g_h2h[(size_t)(row0 + rg + i) * 256 + gc] =
                fmaxf(acc[i][j] + w1b[gc], 0.f);
        }
}

// ------------- batched dec h1l GEMM  M=5120 N=4096 K=128 --------------------
// 256 threads, 64x64 tile, 4x4/thread, register-prefetch pipeline.
__global__ __launch_bounds__(256) void k_dec_h1l() {
    __shared__ float sAT[64][68];
    __shared__ float sB[64][68];
    int col0 = blockIdx.x << 6, row0 = blockIdx.y << 6;
    int tid = threadIdx.x, rg = (tid >> 4) << 2, cg = (tid & 15) << 2;
    float acc[4][4] = {};
    float pa[16], pb[16];
#pragma unroll
    for (int it = 0; it < 16; it++) {
        int i = tid + (it << 8);
        int row = i >> 6, kk = i & 63;
        pa[it] = g_dech2all[(size_t)(row0 + row) * 128 + kk];
        int bkk = i >> 6, bcol = i & 63;
        pb[it] = g_w1d[(size_t)bkk * 4096 + col0 + bcol];
    }
    for (int k0 = 0; k0 < 128; k0 += 64) {
        __syncthreads();
#pragma unroll
        for (int it = 0; it < 16; it++) {
            int i = tid + (it << 8);
            int row = i >> 6, kk = i & 63;
            sAT[kk][row] = pa[it];
            sB[i >> 6][i & 63] = pb[it];
        }
        __syncthreads();
        if (k0 + 64 < 128) {
#pragma unroll
            for (int it = 0; it < 16; it++) {
                int i = tid + (it << 8);
                int row = i >> 6, kk = i & 63;
                pa[it] = g_dech2all[(size_t)(row0 + row) * 128 + 64 + kk];
                pb[it] = g_w1d[(size_t)(64 + (i >> 6)) * 4096 + col0 + (i & 63)];
            }
        }
#pragma unroll 8
        for (int kk = 0; kk < 64; kk++) {
            float4 av = *(const float4*)&sAT[kk][rg];
            float4 bv = *(const float4*)&sB[kk][cg];
            float a[4] = {av.x, av.y, av.z, av.w};
            float b[4] = {bv.x, bv.y, bv.z, bv.w};
#pragma unroll
            for (int i = 0; i < 4; i++)
#pragma unroll
                for (int j = 0; j < 4; j++) acc[i][j] += a[i] * b[j];
        }
    }
#pragma unroll
    for (int i = 0; i < 4; i++) {
        float4 r;
        r.x = acc[i][0]; r.y = acc[i][1]; r.z = acc[i][2]; r.w = acc[i][3];
        *(float4*)&g_h1l[(size_t)(row0 + rg + i) * 4096 + col0 + cg] = r;
    }
}

// ---------------- fused encoder h2 recurrence (19 steps) --------------------
__global__ __launch_bounds__(256) void k_h2chain(const float* __restrict__ linb) {
    __shared__ float s[4][260];
    int o = threadIdx.x, b0 = blockIdx.x * 4;
    float lb = linb[o];
    for (int r = 0; r < 4; r++) s[r][o] = g_h2h[(size_t)(b0 + r) * 256 + o];
    __syncthreads();
    for (int t = 1; t <= 18; t++) {
        float a0 = 0, a1 = 0, a2 = 0, a3 = 0;
        for (int k = 0; k < 256; k += 4) {
            float l0 = g_linT[(k + 0) * 256 + o], l1 = g_linT[(k + 1) * 256 + o];
            float l2 = g_linT[(k + 2) * 256 + o], l3 = g_linT[(k + 3) * 256 + o];
            float4 v0 = *(float4*)&s[0][k], v1 = *(float4*)&s[1][k];
            float4 v2 = *(float4*)&s[2][k], v3 = *(float4*)&s[3][k];
            a0 += v0.x * l0 + v0.y * l1 + v0.z * l2 + v0.w * l3;
            a1 += v1.x * l0 + v1.y * l1 + v1.z * l2 + v1.w * l3;
            a2 += v2.x * l0 + v2.y * l1 + v2.z * l2 + v2.w * l3;
            a3 += v3.x * l0 + v3.y * l1 + v3.z * l2 + v3.w * l3;
        }
        const float* hh = g_h2h + (size_t)(t * 256 + b0) * 256;
        float o0 = fmaxf(hh[0 * 256 + o] + a0 + lb, 0.f);
        float o1 = fmaxf(hh[1 * 256 + o] + a1 + lb, 0.f);
        float o2 = fmaxf(hh[2 * 256 + o] + a2 + lb, 0.f);
        float o3 = fmaxf(hh[3 * 256 + o] + a3 + lb, 0.f);
        __syncthreads();
        s[0][o] = o0; s[1][o] = o1; s[2][o] = o2; s[3][o] = o3;
        __syncthreads();
    }
    for (int r = 0; r < 4; r++) g_h2fin[(b0 + r) * 256 + o] = s[r][o];
}

// ---------------- fused decoder h2 chain (20 steps) -------------------------
__global__ __launch_bounds__(128) void k_dech2chain(const float* __restrict__ linb) {
    __shared__ float s[4][132];
    int o = threadIdx.x, b0 = blockIdx.x * 4;
    float lb = linb[o];
    for (int r = 0; r < 4; r++) s[r][o] = g_h2s[(b0 + r) * 128 + o];
    __syncthreads();
    for (int st = 0; st < 20; st++) {
        float a0 = 0, a1 = 0, a2 = 0, a3 = 0;
        for (int k = 0; k < 128; k += 4) {
            float l0 = g_linTD[(k + 0) * 128 + o], l1 = g_linTD[(k + 1) * 128 + o];
            float l2 = g_linTD[(k + 2) * 128 + o], l3 = g_linTD[(k + 3) * 128 + o];
            float4 v0 = *(float4*)&s[0][k], v1 = *(float4*)&s[1][k];
            float4 v2 = *(float4*)&s[2][k], v3 = *(float4*)&s[3][k];
            a0 += v0.x * l0 + v0.y * l1 + v0.z * l2 + v0.w * l3;
            a1 += v1.x * l0 + v1.y * l1 + v1.z * l2 + v1.w * l3;
            a2 += v2.x * l0 + v2.y * l1 + v2.z * l2 + v2.w * l3;
            a3 += v3.x * l0 + v3.y * l1 + v3.z * l2 + v3.w * l3;
        }
        float o0 = fmaxf(a0 + lb, 0.f), o1 = fmaxf(a1 + lb, 0.f);
        float o2 = fmaxf(a2 + lb, 0.f), o3 = fmaxf(a3 + lb, 0.f);
        float* dst = g_dech2all + (size_t)(st * 256 + b0) * 128;
        dst[0 * 128 + o] = o0; dst[1 * 128 + o] = o1;
        dst[2 * 128 + o] = o2; dst[3 * 128 + o] = o3;
        __syncthreads();
        s[0][o] = o0; s[1][o] = o1; s[2][o] = o2; s[3][o] = o3;
        __syncthreads();
    }
}

// ------------------------------- VQ -----------------------------------------
__global__ __launch_bounds__(256) void k_vq(const float* __restrict__ h1,
                                            const float* __restrict__ emb) {
    __shared__ float sz[64][65];
    __shared__ float se[64][65];
    __shared__ float sesq[64];
    __shared__ float rbest[256];
    __shared__ int ribest[256];
    __shared__ float rsum[256];
    int b = blockIdx.x, tid = threadIdx.x;
    for (int i = tid; i < 4096; i += 256) sz[i >> 6][i & 63] = h1[(size_t)b * 4096 + i];
    __syncthreads();
    int pos = tid & 63, sub = tid >> 6;
    float best = 3.4e38f; int besti = 0;
    for (int k0 = 0; k0 < NK; k0 += 64) {
        for (int i = tid; i < 4096; i += 256)
            se[i >> 6][i & 63] = emb[(size_t)(k0 + (i >> 6)) * 64 + (i & 63)];
        if (tid < 64) sesq[tid] = g_embsq[k0 + tid];
        __syncthreads();
#pragma unroll 2
        for (int jj = 0; jj < 16; jj++) {
            int j = sub * 16 + jj;
            float dot = 0.f;
#pragma unroll
            for (int c = 0; c < 64; c++) dot += sz[pos][c] * se[j][c];
            float score = sesq[j] - 2.f * dot;
            int gidx = k0 + j;
            if (score < best || (score == best && gidx < besti)) { best = score; besti = gidx; }
        }
        __syncthreads();
    }
    rbest[tid] = best; ribest[tid] = besti;
    __syncthreads();
    if (sub == 0) {
        for (int s = 1; s < 4; s++) {
            float bs = rbest[pos + s * 64]; int bi = ribest[pos + s * 64];
            if (bs < best || (bs == best && bi < besti)) { best = bs; besti = bi; }
        }
        ribest[pos] = besti;
    }
    __syncthreads();
    besti = ribest[pos];
    float lsum = 0.f;
    const float* ev = emb + (size_t)besti * 64;
    float* qv = g_q + (size_t)b * 4096 + pos * 64;
#pragma unroll
    for (int cc = 0; cc < 16; cc++) {
        int c = sub * 16 + cc;
        float e = ev[c];
        float d = e - sz[pos][c];
        lsum += d * d;
        qv[c] = e;
    }
    if (sub == 0) atomicAdd(&g_counts[besti], 1);
    rsum[tid] = lsum;
    __syncthreads();
    for (int s = 128; s > 0; s >>= 1) {
        if (tid < s) rsum[tid] += rsum[tid + s];
        __syncthreads();
    }
    if (tid == 0) g_vqpart[b] = rsum[0];
}

// --------------------------- KL + reparam -----------------------------------
__global__ void k_kl(const float* __restrict__ eps) {
    __shared__ float red[128];
    int b = blockIdx.x, j = threadIdx.x;
    float mu = g_h2fin[b * 256 + j];
    float lv = g_h2fin[b * 256 + 128 + j];
    float kv = 0.5f * (expf(lv) + mu * mu - 1.f - lv);
    g_h2s[b * 128 + j] = mu + expf(0.5f * lv) * eps[b * 128 + j];
    red[j] = kv;
    __syncthreads();
    for (int s = 64; s > 0; s >>= 1) {
        if (j < s) red[j] += red[j + s];
        __syncthreads();
    }
    if (j == 0) g_klpart[b] = red[0];
}

__global__ void k_scalars(float* __restrict__ out) {
    __shared__ float red[512];
    int tid = threadIdx.x;
    red[tid] = (tid < 256) ? g_vqpart[tid] : 0.f;
    __syncthreads();
    for (int s = 256; s > 0; s >>= 1) { if (tid < s) red[tid] += red[tid + s]; __syncthreads(); }
    float vqsum = red[0];
    __syncthreads();
    red[tid] = (tid < 256) ? g_klpart[tid] : 0.f;
    __syncthreads();
    for (int s = 256; s > 0; s >>= 1) { if (tid < s) red[tid] += red[tid + s]; __syncthreads(); }
    float klsum = red[0];
    __syncthreads();
    float avg = (float)g_counts[tid] * (1.f / 16384.f);
    red[tid] = avg * logf(avg + 1e-10f);
    __syncthreads();
    for (int s = 256; s > 0; s >>= 1) { if (tid < s) red[tid] += red[tid + s]; __syncthreads(); }
    if (tid == 0) {
        out[0] = 0.25f * vqsum / 1048576.f;
        out[1] = klsum / 256.f;
        out[2 + 8404992] = expf(-red[0]);
    }
}

// ----------------------------- emission -------------------------------------
__global__ __launch_bounds__(256) void k_emit(const float* __restrict__ w0,
                                              const float* __restrict__ bias,
                                              float* __restrict__ xout) {
    __shared__ float srow[64][65];
    __shared__ float sw[IMG];
    __shared__ float simg[IMG];
    int blk = blockIdx.x;
    int s = blk / 256, b = blk % 256;
    int tid = threadIdx.x;
    const float* hp = g_hist + ((size_t)s * 256 + b) * 4096;
    for (int i = tid; i < 4096; i += 256) srow[i >> 6][i & 63] = hp[i];
    for (int i = tid; i < IMG; i += 256) sw[i] = w0[i];
    __syncthreads();
    int p = tid & 63, sub = tid >> 6;
    int n0 = sub * 7;
    int ncount = (sub == 3) ? 6 : 7;
    int nn[7];
#pragma unroll
    for (int q = 0; q < 7; q++) { int n = n0 + q; nn[q] = (n < 27) ? n : 0; }
    float acc[7] = {};
    for (int c = 0; c < 64; c++) {
        float a = srow[p][c];
        const float* swc = sw + c * 27;
#pragma unroll
        for (int q = 0; q < 7; q++) acc[q] += a * swc[nn[q]];
    }
    int h3 = (p >> 3) * 3, w3 = (p & 7) * 3;
    for (int q = 0; q < ncount; q++) {
        int n = n0 + q;
        int oc = n / 9, r = (n % 9) / 3, cl = n % 3;
        float vv = acc[q] + bias[oc];
        vv = vv > 0.f ? vv : expf(vv) - 1.f;
        simg[oc * 576 + (h3 + r) * 24 + w3 + cl] = vv;
    }
    __syncthreads();
    float* op = xout + (size_t)(b * 19 + s) * IMG;
    for (int i = tid; i < IMG; i += 256) op[i] = simg[i];
}

// ------------------------------- host ---------------------------------------
extern "C" void kernel_launch(void* const* d_in, const int* in_sizes, int n_in,
                              void* d_out, int out_size) {
    const float* x        = (const float*)d_in[0];
    const float* eps      = (const float*)d_in[1];
    const float* emb      = (const float*)d_in[2];
    const float* enc_w0   = (const float*)d_in[3];
    const float* enc_w0_b = (const float*)d_in[4];
    const float* enc_w1   = (const float*)d_in[5];
    const float* enc_w1_b = (const float*)d_in[6];
    const float* enc_r0   = (const float*)d_in[7];
    const float* enc_r0_b = (const float*)d_in[8];
    const float* enc_lin_w= (const float*)d_in[9];
    const float* enc_lin_b= (const float*)d_in[10];
    const float* dec_w0   = (const float*)d_in[11];
    const float* dec_w0_b = (const float*)d_in[12];
    const float* dec_w1   = (const float*)d_in[13];
    const float* dec_w1_b = (const float*)d_in[14];
    const float* dec_r0   = (const float*)d_in[15];
    const float* dec_r0_b = (const float*)d_in[16];
    const float* dec_lin_w= (const float*)d_in[17];
    const float* dec_lin_b= (const float*)d_in[18];
    float* out = (float*)d_out;

    float *pc0, *ph1all, *pq, *ph1l, *phist;
    cudaGetSymbolAddress((void**)&pc0, g_c0);
    cudaGetSymbolAddress((void**)&ph1all, g_h1all);
    cudaGetSymbolAddress((void**)&pq, g_q);
    cudaGetSymbolAddress((void**)&ph1l, g_h1l);
    cudaGetSymbolAddress((void**)&phist, g_hist);

    static int attr_done = 0;
    if (!attr_done) {
        cudaFuncSetAttribute(k_contract,
                             cudaFuncAttributeMaxDynamicSharedMemorySize, 69632);
        attr_done = 1;
    }

    k_init<<<1, 512>>>();
    k_pre<<<6466, 256>>>(enc_w1, dec_w1, enc_lin_w, dec_lin_w, emb);
    k_conv0<<<TT * BB, 256>>>(x, enc_w0, enc_w0_b);

    k_chain<<<256, 128>>>(enc_r0, pc0, pc0, enc_r0_b, nullptr, ph1all, 0);
    k_contract<<<dim3(4, 76), 256, 69632>>>(enc_w1_b);
    k_h2chain<<<64, 256>>>(enc_lin_b);

    k_vq<<<256, 256>>>(ph1all + (size_t)18 * 1048576, emb);
    k_kl<<<256, 128>>>(eps);
    k_scalars<<<1, 512>>>(out);

    k_dech2chain<<<64, 128>>>(dec_lin_b);
    k_dec_h1l<<<dim3(64, 80), 256>>>();
    k_chain<<<256, 128>>>(dec_r0, ph1l, pq, dec_r0_b, dec_w1_b, phist, 1);
    k_emit<<<TT * BB, 256>>>(dec_w0, dec_w0_b, out + 2);
    (void)in_sizes; (void)n_in; (void)out_size;
}

// round 14
// speedup vs baseline: 1.2002x; 1.2002x over previous
#include <cuda_runtime.h>
#include <cstddef>

#define BB 256
#define TT 19
#define NK 512
#define IMG 1728
#define PREPB 6468   // prep blocks: 6468*256 = 1655808 >= 1655296+NK

// ------------------------- scratch -------------------------
__device__ float g_c0[(size_t)TT * 1048576];
__device__ float g_h1all[(size_t)TT * 1048576];
__device__ float g_h2h[4864 * 256];
__device__ float g_h2fin[BB * 256];
__device__ float g_w1e[1048576];
__device__ float g_w1d[524288];
__device__ float g_linT[65536];
__device__ float g_linTD[16384];
__device__ float g_embsq[NK];
__device__ float g_q[1048576];
__device__ int   g_counts[NK];
__device__ float g_vqpart[BB];
__device__ float g_klpart[BB];
__device__ float g_h2s[BB * 128];
__device__ float g_dech2all[20 * BB * 128];
__device__ float g_h1l[(size_t)20 * 1048576];
__device__ float g_hist[(size_t)19 * 1048576];

// ---------- merged init + weight prep + conv0 (independent work) ------------
__global__ __launch_bounds__(256) void k_prec(const float* __restrict__ encw1,
                                              const float* __restrict__ decw1,
                                              const float* __restrict__ enclin,
                                              const float* __restrict__ declin,
                                              const float* __restrict__ emb,
                                              const float* __restrict__ x,
                                              const float* __restrict__ w,
                                              const float* __restrict__ bias) {
    int bid = blockIdx.x;
    if (bid < PREPB) {
        int i = bid * 256 + threadIdx.x;
        if (i < 1048576) {
            int o = i >> 12, rem = i & 4095, p = rem >> 6, c = rem & 63;
            g_w1e[i] = encw1[(o << 12) + (c << 6) + p];
        } else if (i < 1572864) {
            int j = i - 1048576;
            int c = j >> 12, rem = j & 4095, p = rem >> 6, o = rem & 63;
            g_w1d[j] = decw1[(c << 12) + (o << 6) + p];
        } else if (i < 1638400) {
            int j = i - 1572864; int k = j >> 8, o = j & 255;
            g_linT[j] = enclin[o * 256 + k];
        } else if (i < 1654784) {
            int j = i - 1638400; int k = j >> 7, o = j & 127;
            g_linTD[j] = declin[o * 128 + k];
        } else if (i < 1655296) {
            int k = i - 1654784;
            float s = 0.f;
            for (int c = 0; c < 64; c++) { float e = emb[k * 64 + c]; s += e * e; }
            g_embsq[k] = s;
        } else if (i < 1655296 + NK) {
            g_counts[i - 1655296] = 0;
        }
        return;
    }
    // ---- conv0 part ----
    __shared__ float sx[IMG];
    __shared__ float sw[IMG];
    int cb = bid - PREPB;
    int t = cb % TT, b = cb / TT;
    const float* xp = x + (size_t)(b * TT + t) * IMG;
    int tid = threadIdx.x;
    for (int i = tid; i < IMG; i += 256) { sx[i] = xp[i]; sw[i] = w[i]; }
    __syncthreads();
    int o = tid & 63, pg = tid >> 6;
    float wr[27];
#pragma unroll
    for (int u = 0; u < 27; u++) wr[u] = sw[o * 27 + u];
    float bo = bias[o];
    float* outp = g_c0 + ((size_t)t * BB + b) * 4096;
#pragma unroll
    for (int k = 0; k < 16; k++) {
        int p = pg + 4 * k, h = p >> 3, ww = p & 7;
        const float* xb = sx + h * 72 + ww * 3;
        float acc = bo;
#pragma unroll
        for (int c = 0; c < 3; c++)
#pragma unroll
            for (int ki = 0; ki < 3; ki++)
#pragma unroll
                for (int kj = 0; kj < 3; kj++)
                    acc += xb[c * 576 + ki * 24 + kj] * wr[c * 9 + ki * 3 + kj];
        outp[p * 64 + o] = acc;
    }
}

// ------------- fused h1 recurrence chain (enc mode=0 / dec mode=1) ----------
__global__ __launch_bounds__(128) void k_chain(const float* __restrict__ R,
                                               const float* __restrict__ addb,
                                               const float* __restrict__ initp,
                                               const float* __restrict__ b1,
                                               const float* __restrict__ b2,
                                               float* __restrict__ outb,
                                               int mode) {
    __shared__ float shA[2][64][68];
    __shared__ float sR[64][68];
    int tid = threadIdx.x;
    int row0 = blockIdx.x * 64;
    int rg = (tid >> 4) << 3;
    int cg = (tid & 15) << 2;
    for (int q = tid; q < 4096; q += 128) sR[q & 63][q >> 6] = R[q];
    float bias[4];
#pragma unroll
    for (int j = 0; j < 4; j++) bias[j] = b1[cg + j] + (b2 ? b2[cg + j] : 0.f);
    for (int q = tid; q < 1024; q += 128) {
        int r = q >> 4, c4 = (q & 15) << 2;
        float4 v = *(const float4*)&initp[(size_t)(row0 + r) * 64 + c4];
        if (!mode) {
            v.x = fmaxf(v.x, 0.f); v.y = fmaxf(v.y, 0.f);
            v.z = fmaxf(v.z, 0.f); v.w = fmaxf(v.w, 0.f);
            *(float4*)&outb[(size_t)(row0 + r) * 64 + c4] = v;
        }
        shA[0][c4][r] = v.x; shA[0][c4 + 1][r] = v.y;
        shA[0][c4 + 2][r] = v.z; shA[0][c4 + 3][r] = v.w;
    }
    __syncthreads();
    int tot = mode ? 20 : 18;
    int cur = 0;
    for (int it = 0; it < tot; it++) {
        int t = mode ? it : it + 1;
        float acc[8][4];
#pragma unroll
        for (int i = 0; i < 8; i++)
#pragma unroll
            for (int j = 0; j < 4; j++) acc[i][j] = 0.f;
#pragma unroll 4
        for (int c = 0; c < 64; c++) {
            float4 a0 = *(float4*)&shA[cur][c][rg];
            float4 a1 = *(float4*)&shA[cur][c][rg + 4];
            float4 w = *(float4*)&sR[c][cg];
            float av[8] = {a0.x, a0.y, a0.z, a0.w, a1.x, a1.y, a1.z, a1.w};
            float wv[4] = {w.x, w.y, w.z, w.w};
#pragma unroll
            for (int i = 0; i < 8; i++)
#pragma unroll
                for (int j = 0; j < 4; j++) acc[i][j] += av[i] * wv[j];
        }
        const float* add = addb + (size_t)t * 1048576;
        float* op = mode ? (t >= 1 ? outb + (size_t)(t - 1) * 1048576 : (float*)0)
                         : outb + (size_t)t * 1048576;
        int nxt = cur ^ 1;
#pragma unroll
        for (int i = 0; i < 8; i++) {
            int r = row0 + rg + i;
            float4 ad = *(const float4*)&add[(size_t)r * 64 + cg];
            float4 res;
            res.x = fmaxf(acc[i][0] + ad.x + bias[0], 0.f);
            res.y = fmaxf(acc[i][1] + ad.y + bias[1], 0.f);
            res.z = fmaxf(acc[i][2] + ad.z + bias[2], 0.f);
            res.w = fmaxf(acc[i][3] + ad.w + bias[3], 0.f);
            if (op) *(float4*)&op[(size_t)r * 64 + cg] = res;
            shA[nxt][cg][rg + i] = res.x; shA[nxt][cg + 1][rg + i] = res.y;
            shA[nxt][cg + 2][rg + i] = res.z; shA[nxt][cg + 3][rg + i] = res.w;
        }
        cur = nxt;
        __syncthreads();
    }
}

// ------------- batched contract GEMM  M=4864 N=256 K=4096 -------------------
// 256 threads, 64x64 tile, 4x4/thread, register-prefetch pipeline.
__global__ __launch_bounds__(256) void k_contract(const float* __restrict__ w1b) {
    __shared__ float sAT[64][68];
    __shared__ float sB[64][68];
    int col0 = blockIdx.x << 6, row0 = blockIdx.y << 6;
    int tid = threadIdx.x, rg = (tid >> 4) << 2, cg = (tid & 15) << 2;
    int srow = tid >> 6;
    int skk = tid & 63;
    float acc[4][4] = {};
    float pa[16], pb[16];
#pragma unroll
    for (int it = 0; it < 16; it++) {
        int row = srow + (it << 2);
        pa[it] = g_h1all[(size_t)(row0 + row) * 4096 + skk];
        pb[it] = g_w1e[(size_t)(col0 + row) * 4096 + skk];
    }
    for (int k0 = 0; k0 < 4096; k0 += 64) {
        __syncthreads();
#pragma unroll
        for (int it = 0; it < 16; it++) {
            int row = srow + (it << 2);
            sAT[skk][row] = pa[it];
            sB[skk][row] = pb[it];
        }
        __syncthreads();
        if (k0 + 64 < 4096) {
#pragma unroll
            for (int it = 0; it < 16; it++) {
                int row = srow + (it << 2);
                pa[it] = g_h1all[(size_t)(row0 + row) * 4096 + k0 + 64 + skk];
                pb[it] = g_w1e[(size_t)(col0 + row) * 4096 + k0 + 64 + skk];
            }
        }
#pragma unroll 8
        for (int kk = 0; kk < 64; kk++) {
            float4 av = *(const float4*)&sAT[kk][rg];
            float4 bv = *(const float4*)&sB[kk][cg];
            float a[4] = {av.x, av.y, av.z, av.w};
            float b[4] = {bv.x, bv.y, bv.z, bv.w};
#pragma unroll
            for (int i = 0; i < 4; i++)
#pragma unroll
                for (int j = 0; j < 4; j++) acc[i][j] += a[i] * b[j];
        }
    }
#pragma unroll
    for (int i = 0; i < 4; i++)
#pragma unroll
        for (int j = 0; j < 4; j++) {
            int gc = col0 + cg + j;
            g_h2h[(size_t)(row0 + rg + i) * 256 + gc] =
                fmaxf(acc[i][j] + w1b[gc], 0.f);
        }
}

// ---------- merged: enc h2 recurrence (blocks 0..63) + VQ (blocks 64..319) --
__global__ __launch_bounds__(256) void k_h2vq(const float* __restrict__ linb,
                                              const float* __restrict__ h1,
                                              const float* __restrict__ emb) {
    int bid = blockIdx.x;
    if (bid < 64) {
        // ---- h2chain ----
        __shared__ float s[4][260];
        int o = threadIdx.x, b0 = bid * 4;
        float lb = linb[o];
        for (int r = 0; r < 4; r++) s[r][o] = g_h2h[(size_t)(b0 + r) * 256 + o];
        __syncthreads();
        for (int t = 1; t <= 18; t++) {
            float a0 = 0, a1 = 0, a2 = 0, a3 = 0;
            for (int k = 0; k < 256; k += 4) {
                float l0 = g_linT[(k + 0) * 256 + o], l1 = g_linT[(k + 1) * 256 + o];
                float l2 = g_linT[(k + 2) * 256 + o], l3 = g_linT[(k + 3) * 256 + o];
                float4 v0 = *(float4*)&s[0][k], v1 = *(float4*)&s[1][k];
                float4 v2 = *(float4*)&s[2][k], v3 = *(float4*)&s[3][k];
                a0 += v0.x * l0 + v0.y * l1 + v0.z * l2 + v0.w * l3;
                a1 += v1.x * l0 + v1.y * l1 + v1.z * l2 + v1.w * l3;
                a2 += v2.x * l0 + v2.y * l1 + v2.z * l2 + v2.w * l3;
                a3 += v3.x * l0 + v3.y * l1 + v3.z * l2 + v3.w * l3;
            }
            const float* hh = g_h2h + (size_t)(t * 256 + b0) * 256;
            float o0 = fmaxf(hh[0 * 256 + o] + a0 + lb, 0.f);
            float o1 = fmaxf(hh[1 * 256 + o] + a1 + lb, 0.f);
            float o2 = fmaxf(hh[2 * 256 + o] + a2 + lb, 0.f);
            float o3 = fmaxf(hh[3 * 256 + o] + a3 + lb, 0.f);
            __syncthreads();
            s[0][o] = o0; s[1][o] = o1; s[2][o] = o2; s[3][o] = o3;
            __syncthreads();
        }
        for (int r = 0; r < 4; r++) g_h2fin[(b0 + r) * 256 + o] = s[r][o];
        return;
    }
    // ---- VQ ----
    __shared__ float sz[64][65];
    __shared__ float se[64][65];
    __shared__ float sesq[64];
    __shared__ float rbest[256];
    __shared__ int ribest[256];
    __shared__ float rsum[256];
    int b = bid - 64, tid = threadIdx.x;
    for (int i = tid; i < 4096; i += 256) sz[i >> 6][i & 63] = h1[(size_t)b * 4096 + i];
    __syncthreads();
    int pos = tid & 63, sub = tid >> 6;
    float best = 3.4e38f; int besti = 0;
    for (int k0 = 0; k0 < NK; k0 += 64) {
        for (int i = tid; i < 4096; i += 256)
            se[i >> 6][i & 63] = emb[(size_t)(k0 + (i >> 6)) * 64 + (i & 63)];
        if (tid < 64) sesq[tid] = g_embsq[k0 + tid];
        __syncthreads();
#pragma unroll 2
        for (int jj = 0; jj < 16; jj++) {
            int j = sub * 16 + jj;
            float dot = 0.f;
#pragma unroll
            for (int c = 0; c < 64; c++) dot += sz[pos][c] * se[j][c];
            float score = sesq[j] - 2.f * dot;
            int gidx = k0 + j;
            if (score < best || (score == best && gidx < besti)) { best = score; besti = gidx; }
        }
        __syncthreads();
    }
    rbest[tid] = best; ribest[tid] = besti;
    __syncthreads();
    if (sub == 0) {
        for (int s = 1; s < 4; s++) {
            float bs = rbest[pos + s * 64]; int bi = ribest[pos + s * 64];
            if (bs < best || (bs == best && bi < besti)) { best = bs; besti = bi; }
        }
        ribest[pos] = besti;
    }
    __syncthreads();
    besti = ribest[pos];
    float lsum = 0.f;
    const float* ev = emb + (size_t)besti * 64;
    float* qv = g_q + (size_t)b * 4096 + pos * 64;
#pragma unroll
    for (int cc = 0; cc < 16; cc++) {
        int c = sub * 16 + cc;
        float e = ev[c];
        float d = e - sz[pos][c];
        lsum += d * d;
        qv[c] = e;
    }
    if (sub == 0) atomicAdd(&g_counts[besti], 1);
    rsum[tid] = lsum;
    __syncthreads();
    for (int s = 128; s > 0; s >>= 1) {
        if (tid < s) rsum[tid] += rsum[tid + s];
        __syncthreads();
    }
    if (tid == 0) g_vqpart[b] = rsum[0];
}

// ------------- batched dec h1l GEMM  M=5120 N=4096 K=128 --------------------
__global__ __launch_bounds__(256) void k_dec_h1l() {
    __shared__ float sAT[64][68];
    __shared__ float sB[64][68];
    int col0 = blockIdx.x << 6, row0 = blockIdx.y << 6;
    int tid = threadIdx.x, rg = (tid >> 4) << 2, cg = (tid & 15) << 2;
    float acc[4][4] = {};
    float pa[16], pb[16];
#pragma unroll
    for (int it = 0; it < 16; it++) {
        int i = tid + (it << 8);
        int row = i >> 6, kk = i & 63;
        pa[it] = g_dech2all[(size_t)(row0 + row) * 128 + kk];
        pb[it] = g_w1d[(size_t)(i >> 6) * 4096 + col0 + (i & 63)];
    }
    for (int k0 = 0; k0 < 128; k0 += 64) {
        __syncthreads();
#pragma unroll
        for (int it = 0; it < 16; it++) {
            int i = tid + (it << 8);
            sAT[i & 63][i >> 6] = pa[it];
            sB[i >> 6][i & 63] = pb[it];
        }
        __syncthreads();
        if (k0 + 64 < 128) {
#pragma unroll
            for (int it = 0; it < 16; it++) {
                int i = tid + (it << 8);
                int row = i >> 6, kk = i & 63;
                pa[it] = g_dech2all[(size_t)(row0 + row) * 128 + 64 + kk];
                pb[it] = g_w1d[(size_t)(64 + (i >> 6)) * 4096 + col0 + (i & 63)];
            }
        }
#pragma unroll 8
        for (int kk = 0; kk < 64; kk++) {
            float4 av = *(const float4*)&sAT[kk][rg];
            float4 bv = *(const float4*)&sB[kk][cg];
            float a[4] = {av.x, av.y, av.z, av.w};
            float b[4] = {bv.x, bv.y, bv.z, bv.w};
#pragma unroll
            for (int i = 0; i < 4; i++)
#pragma unroll
                for (int j = 0; j < 4; j++) acc[i][j] += a[i] * b[j];
        }
    }
#pragma unroll
    for (int i = 0; i < 4; i++) {
        float4 r;
        r.x = acc[i][0]; r.y = acc[i][1]; r.z = acc[i][2]; r.w = acc[i][3];
        *(float4*)&g_h1l[(size_t)(row0 + rg + i) * 4096 + col0 + cg] = r;
    }
}

// ---------------- fused decoder h2 chain (20 steps) -------------------------
__global__ __launch_bounds__(128) void k_dech2chain(const float* __restrict__ linb) {
    __shared__ float s[4][132];
    int o = threadIdx.x, b0 = blockIdx.x * 4;
    float lb = linb[o];
    for (int r = 0; r < 4; r++) s[r][o] = g_h2s[(b0 + r) * 128 + o];
    __syncthreads();
    for (int st = 0; st < 20; st++) {
        float a0 = 0, a1 = 0, a2 = 0, a3 = 0;
        for (int k = 0; k < 128; k += 4) {
            float l0 = g_linTD[(k + 0) * 128 + o], l1 = g_linTD[(k + 1) * 128 + o];
            float l2 = g_linTD[(k + 2) * 128 + o], l3 = g_linTD[(k + 3) * 128 + o];
            float4 v0 = *(float4*)&s[0][k], v1 = *(float4*)&s[1][k];
            float4 v2 = *(float4*)&s[2][k], v3 = *(float4*)&s[3][k];
            a0 += v0.x * l0 + v0.y * l1 + v0.z * l2 + v0.w * l3;
            a1 += v1.x * l0 + v1.y * l1 + v1.z * l2 + v1.w * l3;
            a2 += v2.x * l0 + v2.y * l1 + v2.z * l2 + v2.w * l3;
            a3 += v3.x * l0 + v3.y * l1 + v3.z * l2 + v3.w * l3;
        }
        float o0 = fmaxf(a0 + lb, 0.f), o1 = fmaxf(a1 + lb, 0.f);
        float o2 = fmaxf(a2 + lb, 0.f), o3 = fmaxf(a3 + lb, 0.f);
        float* dst = g_dech2all + (size_t)(st * 256 + b0) * 128;
        dst[0 * 128 + o] = o0; dst[1 * 128 + o] = o1;
        dst[2 * 128 + o] = o2; dst[3 * 128 + o] = o3;
        __syncthreads();
        s[0][o] = o0; s[1][o] = o1; s[2][o] = o2; s[3][o] = o3;
        __syncthreads();
    }
}

// --------------------------- KL + reparam -----------------------------------
__global__ void k_kl(const float* __restrict__ eps) {
    __shared__ float red[128];
    int b = blockIdx.x, j = threadIdx.x;
    float mu = g_h2fin[b * 256 + j];
    float lv = g_h2fin[b * 256 + 128 + j];
    float kv = 0.5f * (expf(lv) + mu * mu - 1.f - lv);
    g_h2s[b * 128 + j] = mu + expf(0.5f * lv) * eps[b * 128 + j];
    red[j] = kv;
    __syncthreads();
    for (int s = 64; s > 0; s >>= 1) {
        if (j < s) red[j] += red[j + s];
        __syncthreads();
    }
    if (j == 0) g_klpart[b] = red[0];
}

__global__ void k_scalars(float* __restrict__ out) {
    __shared__ float red[512];
    int tid = threadIdx.x;
    red[tid] = (tid < 256) ? g_vqpart[tid] : 0.f;
    __syncthreads();
    for (int s = 256; s > 0; s >>= 1) { if (tid < s) red[tid] += red[tid + s]; __syncthreads(); }
    float vqsum = red[0];
    __syncthreads();
    red[tid] = (tid < 256) ? g_klpart[tid] : 0.f;
    __syncthreads();
    for (int s = 256; s > 0; s >>= 1) { if (tid < s) red[tid] += red[tid + s]; __syncthreads(); }
    float klsum = red[0];
    __syncthreads();
    float avg = (float)g_counts[tid] * (1.f / 16384.f);
    red[tid] = avg * logf(avg + 1e-10f);
    __syncthreads();
    for (int s = 256; s > 0; s >>= 1) { if (tid < s) red[tid] += red[tid + s]; __syncthreads(); }
    if (tid == 0) {
        out[0] = 0.25f * vqsum / 1048576.f;
        out[1] = klsum / 256.f;
        out[2 + 8404992] = expf(-red[0]);
    }
}

// ----------------------------- emission -------------------------------------
__global__ __launch_bounds__(256) void k_emit(const float* __restrict__ w0,
                                              const float* __restrict__ bias,
                                              float* __restrict__ xout) {
    __shared__ float srow[64][65];
    __shared__ float sw[IMG];
    __shared__ float simg[IMG];
    int blk = blockIdx.x;
    int s = blk / 256, b = blk % 256;
    int tid = threadIdx.x;
    const float* hp = g_hist + ((size_t)s * 256 + b) * 4096;
    for (int i = tid; i < 4096; i += 256) srow[i >> 6][i & 63] = hp[i];
    for (int i = tid; i < IMG; i += 256) sw[i] = w0[i];
    __syncthreads();
    int p = tid & 63, sub = tid >> 6;
    int n0 = sub * 7;
    int ncount = (sub == 3) ? 6 : 7;
    int nn[7];
#pragma unroll
    for (int q = 0; q < 7; q++) { int n = n0 + q; nn[q] = (n < 27) ? n : 0; }
    float acc[7] = {};
    for (int c = 0; c < 64; c++) {
        float a = srow[p][c];
        const float* swc = sw + c * 27;
#pragma unroll
        for (int q = 0; q < 7; q++) acc[q] += a * swc[nn[q]];
    }
    int h3 = (p >> 3) * 3, w3 = (p & 7) * 3;
    for (int q = 0; q < ncount; q++) {
        int n = n0 + q;
        int oc = n / 9, r = (n % 9) / 3, cl = n % 3;
        float vv = acc[q] + bias[oc];
        vv = vv > 0.f ? vv : expf(vv) - 1.f;
        simg[oc * 576 + (h3 + r) * 24 + w3 + cl] = vv;
    }
    __syncthreads();
    float* op = xout + (size_t)(b * 19 + s) * IMG;
    for (int i = tid; i < IMG; i += 256) op[i] = simg[i];
}

// ------------------------------- host ---------------------------------------
extern "C" void kernel_launch(void* const* d_in, const int* in_sizes, int n_in,
                              void* d_out, int out_size) {
    const float* x        = (const float*)d_in[0];
    const float* eps      = (const float*)d_in[1];
    const float* emb      = (const float*)d_in[2];
    const float* enc_w0   = (const float*)d_in[3];
    const float* enc_w0_b = (const float*)d_in[4];
    const float* enc_w1   = (const float*)d_in[5];
    const float* enc_w1_b = (const float*)d_in[6];
    const float* enc_r0   = (const float*)d_in[7];
    const float* enc_r0_b = (const float*)d_in[8];
    const float* enc_lin_w= (const float*)d_in[9];
    const float* enc_lin_b= (const float*)d_in[10];
    const float* dec_w0   = (const float*)d_in[11];
    const float* dec_w0_b = (const float*)d_in[12];
    const float* dec_w1   = (const float*)d_in[13];
    const float* dec_w1_b = (const float*)d_in[14];
    const float* dec_r0   = (const float*)d_in[15];
    const float* dec_r0_b = (const float*)d_in[16];
    const float* dec_lin_w= (const float*)d_in[17];
    const float* dec_lin_b= (const float*)d_in[18];
    float* out = (float*)d_out;

    float *pc0, *ph1all, *pq, *ph1l, *phist;
    cudaGetSymbolAddress((void**)&pc0, g_c0);
    cudaGetSymbolAddress((void**)&ph1all, g_h1all);
    cudaGetSymbolAddress((void**)&pq, g_q);
    cudaGetSymbolAddress((void**)&ph1l, g_h1l);
    cudaGetSymbolAddress((void**)&phist, g_hist);

    k_prec<<<PREPB + TT * BB, 256>>>(enc_w1, dec_w1, enc_lin_w, dec_lin_w, emb,
                                     x, enc_w0, enc_w0_b);

    k_chain<<<256, 128>>>(enc_r0, pc0, pc0, enc_r0_b, nullptr, ph1all, 0);
    k_contract<<<dim3(4, 76), 256>>>(enc_w1_b);
    k_h2vq<<<320, 256>>>(enc_lin_b, ph1all + (size_t)18 * 1048576, emb);

    k_kl<<<256, 128>>>(eps);
    k_scalars<<<1, 512>>>(out);

    k_dech2chain<<<64, 128>>>(dec_lin_b);
    k_dec_h1l<<<dim3(64, 80), 256>>>();
    k_chain<<<256, 128>>>(dec_r0, ph1l, pq, dec_r0_b, dec_w1_b, phist, 1);
    k_emit<<<TT * BB, 256>>>(dec_w0, dec_w0_b, out + 2);
    (void)in_sizes; (void)n_in; (void)out_size;
}